// round 9
// baseline (speedup 1.0000x reference)
#include <cuda_runtime.h>
#include <cuda_fp16.h>
#include <math.h>
#include <stdint.h>

#define T_STEPS 256
#define B_SZ    256
#define I_SZ    128
#define N_SZ    1024
#define O_SZ    64
#define M_ROWS  512

#define GRID_MAIN 128
#define NTHREADS 512
#define BK 64              // k per chunk (halves)
#define NCHUNK (N_SZ / BK) // 16
#define LSTR 33

#define WSTR_H 1032        // W smem row stride (halves)
#define ASTR_H 72          // A smem row stride (halves)
#define ABUF_B 18432       // one A buffer: 128 * 72 * 2

// ---- shared memory byte offsets ----
#define OFF_W     0                        // 32*1032*2 = 66048
#define OFF_A     66048                    // 3 x 18432 = 55296
#define OFF_SLOC  121344                   // 128*33 floats
#define OFF_XS    138240
#define OFF_KS    155136
#define OFF_FCS   172032
#define OFF_BHS   172160
#define SMEM_BYTES 172288

__device__ __half g_S0[M_ROWS * N_SZ];
__device__ __half g_S1[M_ROWS * N_SZ];
__device__ float  g_X [M_ROWS * N_SZ];
__device__ float  g_F0[B_SZ * N_SZ];
__device__ float  g_fc[N_SZ];
__device__ unsigned g_bar_count[4 * 32];   // per 32-CTA group, 128B apart
__device__ unsigned g_bar_phase[4 * 32];

__constant__ float C_H     = 0.05f;
__constant__ float C_OMEGA = 6.283185307179586f;
__constant__ float C_GAMMA = 0.1f;
__constant__ float C_LAM   = 1.0f;
__constant__ float C_GAIN  = 0.03125f;

// ---------------------------------------------------------------------------
__global__ void init_kernel(const float* __restrict__ b_ih) {
    int idx = blockIdx.x * blockDim.x + threadIdx.x;
    int stride = gridDim.x * blockDim.x;
    for (int i = idx; i < M_ROWS * N_SZ; i += stride) g_S0[i] = __float2half(0.0f);
    if (idx < 4 * 32) { g_bar_count[idx] = 0u; g_bar_phase[idx] = 0u; }
    if (idx < N_SZ) g_fc[idx] = tanhf(b_ih[idx]);
}

__global__ void forcing_kernel(const float* __restrict__ batch,
                               const float* __restrict__ W_ih,
                               const float* __restrict__ b_ih) {
    int idx = blockIdx.x * blockDim.x + threadIdx.x;
    int b = idx >> 10;
    int n = idx & (N_SZ - 1);
    const float4* xp = (const float4*)(batch + b * I_SZ);
    const float4* wp = (const float4*)(W_ih + n * I_SZ);
    float s = 0.0f;
#pragma unroll 8
    for (int i = 0; i < I_SZ / 4; ++i) {
        float4 x = __ldg(xp + i);
        float4 w = __ldg(wp + i);
        s += x.x * w.x + x.y * w.y + x.z * w.z + x.w * w.w;
    }
    g_F0[idx] = tanhf(s + __ldg(b_ih + n));
}

// ---------------------------------------------------------------------------
__device__ __forceinline__ void group_barrier(int grp) {
    __syncthreads();
    if (threadIdx.x == 0) {
        __threadfence();                   // release whole CTA's writes
        volatile unsigned* ph = &g_bar_phase[grp * 32];
        unsigned p = *ph;
        unsigned a = atomicAdd(&g_bar_count[grp * 32], 1u);
        if (a == 31u) {
            atomicExch(&g_bar_count[grp * 32], 0u);
            __threadfence();
            atomicAdd(&g_bar_phase[grp * 32], 1u);
        } else {
            while (*ph == p) { }
        }
        __threadfence();                   // acquire
    }
    __syncthreads();
}

// ---------------------------------------------------------------------------
__device__ __forceinline__ void mma_f16(float* d, uint32_t a0, uint32_t a1,
                                        uint32_t a2, uint32_t a3,
                                        uint32_t b0, uint32_t b1) {
    asm volatile(
        "mma.sync.aligned.m16n8k16.row.col.f32.f16.f16.f32 "
        "{%0,%1,%2,%3},{%4,%5,%6,%7},{%8,%9},{%0,%1,%2,%3};"
        : "+f"(d[0]), "+f"(d[1]), "+f"(d[2]), "+f"(d[3])
        : "r"(a0), "r"(a1), "r"(a2), "r"(a3), "r"(b0), "r"(b1));
}

__device__ __forceinline__ void ldsm4(uint32_t& r0, uint32_t& r1, uint32_t& r2,
                                      uint32_t& r3, uint32_t addr) {
    asm volatile("ldmatrix.sync.aligned.m8n8.x4.shared.b16 {%0,%1,%2,%3}, [%4];"
                 : "=r"(r0), "=r"(r1), "=r"(r2), "=r"(r3) : "r"(addr));
}

__device__ __forceinline__ void cp16(uint32_t s, const void* g) {
    asm volatile("cp.async.cg.shared.global [%0], [%1], 16;"
                 :: "r"(s), "l"(g) : "memory");
}
__device__ __forceinline__ void cp_commit() {
    asm volatile("cp.async.commit_group;" ::: "memory");
}

__device__ __forceinline__ uint32_t smem_u32(const void* p) {
    uint32_t a;
    asm("{ .reg .u64 t; cvta.to.shared.u64 t, %1; cvt.u32.u64 %0, t; }" : "=r"(a) : "l"(p));
    return a;
}

// ---------------------------------------------------------------------------
// main persistent kernel.
// Grid 128 = 4 independent 32-CTA groups. 512 threads = 16 warps, each a
// 16x16 output tile (8 m-strips x 2 n-halves). W resident in SMEM (fp16).
// ---------------------------------------------------------------------------
__global__ void __launch_bounds__(NTHREADS, 1)
main_kernel(const float* __restrict__ W_hh, const float* __restrict__ b_hh) {
    extern __shared__ __align__(16) unsigned char smraw[];
    __half* Wsm = (__half*)(smraw + OFF_W);
    float* Sloc = (float*)(smraw + OFF_SLOC);
    float* Xs   = (float*)(smraw + OFF_XS);
    float* Ks   = (float*)(smraw + OFF_KS);
    float* fcs  = (float*)(smraw + OFF_FCS);
    float* bhs  = (float*)(smraw + OFF_BHS);

    const int tid  = threadIdx.x;
    const int lane = tid & 31;
    const int wid  = tid >> 5;           // 0..15
    const int wm2  = wid >> 1;           // m strip 0..7 (16 rows)
    const int wn2  = wid & 1;            // n half 0..1 (16 cols)
    const int bn   = blockIdx.x & 31;
    const int bm   = blockIdx.x >> 5;
    const int N0   = bn * 32;
    const int batch0 = bm * 64;
    const bool isx = (wid < 8);          // rows 0..63 = x half

    const uint32_t sbase = smem_u32(smraw);
    const uint32_t abase = sbase + OFF_A;

    // ---- one-time: W slice -> smem fp16 ----
    for (int i4 = tid; i4 < 32 * 256; i4 += NTHREADS) {
        int r = i4 >> 8, kpos = (i4 & 255) * 4;
        float4 w = __ldg((const float4*)(W_hh + (N0 + r) * N_SZ + kpos));
        __half2* p = (__half2*)(Wsm + r * WSTR_H + kpos);
        p[0] = __floats2half2_rn(w.x, w.y);
        p[1] = __floats2half2_rn(w.z, w.w);
    }
    for (int i = tid; i < 128 * LSTR; i += NTHREADS) { Sloc[i] = 0.0f; Xs[i] = 0.0f; Ks[i] = 0.0f; }
    if (tid < 32) { fcs[tid] = g_fc[N0 + tid]; bhs[tid] = __ldg(b_hh + N0 + tid); }
    __syncthreads();

    // ---- cp.async loader mapping: 2 x 16B per thread per chunk ----
    int gofs[2];
    uint32_t sofs[2];
    {
        const int cg = tid & 7;
#pragma unroll
        for (int i = 0; i < 2; ++i) {
            int arow = (tid >> 3) + 64 * i;     // 0..127
            int grow = (arow < 64) ? (batch0 + arow) : (256 + batch0 + arow - 64);
            gofs[i] = grow * N_SZ + cg * 8;
            sofs[i] = (uint32_t)(arow * ASTR_H + cg * 8) * 2;
        }
    }

    // ---- ldmatrix lane addresses ----
    const uint32_t aoff_l =
        (uint32_t)(((wm2 * 16 + (lane & 7) + ((lane & 8) ? 8 : 0)) * ASTR_H
                    + ((lane & 16) ? 8 : 0)) * 2);
    const uint32_t woff =
        sbase + OFF_W +
        (uint32_t)(((wn2 * 16 + (lane & 7) + ((lane & 16) ? 8 : 0)) * WSTR_H
                    + ((lane & 8) ? 8 : 0)) * 2);

    __half* const bufs[2] = { g_S0, g_S1 };

    for (int t = 0; t < T_STEPS; ++t) {
        for (int s = 0; s < 4; ++s) {
            const __half* Sin = bufs[s & 1];
            __half*       Sout = bufs[(s + 1) & 1];

            float acc[2][4];
#pragma unroll
            for (int i = 0; i < 2; ++i)
#pragma unroll
                for (int j = 0; j < 4; ++j) acc[i][j] = 0.0f;

            // prologue: chunks 0,1
#pragma unroll
            for (int st = 0; st < 2; ++st) {
                const uint32_t ab = abase + st * ABUF_B;
#pragma unroll
                for (int i = 0; i < 2; ++i)
                    cp16(ab + sofs[i], Sin + gofs[i] + st * BK);
                cp_commit();
            }

            for (int c = 0; c < NCHUNK; ++c) {
                if (c == NCHUNK - 1)
                    asm volatile("cp.async.wait_group 0;" ::: "memory");
                else
                    asm volatile("cp.async.wait_group 1;" ::: "memory");
                __syncthreads();

                if (c + 2 < NCHUNK) {
                    const int st = c + 2;
                    const uint32_t ab = abase + (st % 3) * ABUF_B;
#pragma unroll
                    for (int i = 0; i < 2; ++i)
                        cp16(ab + sofs[i], Sin + gofs[i] + st * BK);
                    cp_commit();
                }

                const uint32_t ab = abase + (c % 3) * ABUF_B;
                const uint32_t wk = (uint32_t)(c * BK * 2);
#pragma unroll
                for (int kk = 0; kk < BK; kk += 16) {
                    uint32_t a0, a1, a2, a3;
                    ldsm4(a0, a1, a2, a3, ab + aoff_l + kk * 2);
                    uint32_t b00, b01, b10, b11;
                    ldsm4(b00, b01, b10, b11, woff + wk + kk * 2);
                    mma_f16(acc[0], a0, a1, a2, a3, b00, b01);
                    mma_f16(acc[1], a0, a1, a2, a3, b10, b11);
                }
            }

            // ---------------- fused RK4-stage epilogue (SMEM-local state) -------
            const float cmul = (s == 2) ? C_H : 0.5f * C_H;
            const int r0 = wm2 * 16 + (lane >> 2);
            float kv[2][4];
#pragma unroll
            for (int nt = 0; nt < 2; ++nt) {
#pragma unroll
                for (int e = 0; e < 4; ++e) {
                    const int rl = r0 + 8 * (e >> 1);
                    const int cl = wn2 * 16 + nt * 8 + 2 * (lane & 3) + (e & 1);
                    const int rx = isx ? rl : rl - 64;
                    const float sx = Sloc[rx * LSTR + cl];
                    const float sy = Sloc[(rx + 64) * LSTR + cl];
                    const float amp = C_LAM - (sx * sx + sy * sy);
                    const float rr = acc[nt][e];
                    float k;
                    if (isx) {
                        float F = (t == 0) ? g_F0[(batch0 + rx) * N_SZ + N0 + cl] : fcs[cl];
                        k = amp * sx - C_OMEGA * sy + C_GAIN * (rr + bhs[cl]) + F - C_GAMMA * sx;
                    } else {
                        k = amp * sy + C_OMEGA * sx + C_GAIN * (rr + bhs[cl]) - C_GAMMA * sy;
                    }
                    kv[nt][e] = k;
                }
            }
            __syncthreads();  // all Sloc reads done before overwrites
#pragma unroll
            for (int nt = 0; nt < 2; ++nt) {
#pragma unroll
                for (int eh = 0; eh < 2; ++eh) {
                    const int rl  = r0 + 8 * eh;
                    const int cl0 = wn2 * 16 + nt * 8 + 2 * (lane & 3);
                    float sv[2];
#pragma unroll
                    for (int j = 0; j < 2; ++j) {
                        const int il = rl * LSTR + cl0 + j;
                        const float k = kv[nt][eh * 2 + j];
                        const float xv = Xs[il];
                        float v;
                        if (s == 0)      { Ks[il] = k;                        v = xv + cmul * k; }
                        else if (s == 3) { float xn = xv + (C_H / 6.0f) * (Ks[il] + k);
                                           Xs[il] = xn;                       v = xn; }
                        else             { Ks[il] += 2.0f * k;                v = xv + cmul * k; }
                        Sloc[il] = v;
                        sv[j] = v;
                    }
                    const int grow = batch0 + rl + (isx ? 0 : 192);
                    const int gi = grow * N_SZ + N0 + cl0;
                    *(__half2*)(Sout + gi) = __floats2half2_rn(sv[0], sv[1]);
                    if (t == T_STEPS - 1 && s == 3)
                        *(float2*)(g_X + gi) = make_float2(sv[0], sv[1]);
                }
            }
            group_barrier(bm);
        }
    }
}

// ---------------------------------------------------------------------------
__global__ void out_kernel(const float* __restrict__ W_ho,
                           const float* __restrict__ b_ho,
                           float* __restrict__ out) {
    int b   = blockIdx.x;
    int tid = threadIdx.x;
    int o   = tid >> 2;
    int q   = tid & 3;
    const float4* xp = (const float4*)(g_X + b * N_SZ + q * 256);
    const float4* wp = (const float4*)(W_ho + o * N_SZ + q * 256);
    float s = 0.0f;
#pragma unroll 8
    for (int i = 0; i < 64; ++i) {
        float4 x = xp[i];
        float4 w = __ldg(wp + i);
        s += x.x * w.x + x.y * w.y + x.z * w.z + x.w * w.w;
    }
    s += __shfl_xor_sync(0xffffffffu, s, 1);
    s += __shfl_xor_sync(0xffffffffu, s, 2);
    if (q == 0) out[b * O_SZ + o] = s + __ldg(b_ho + o);
}

// ---------------------------------------------------------------------------
extern "C" void kernel_launch(void* const* d_in, const int* in_sizes, int n_in,
                              void* d_out, int out_size) {
    const float* batch = (const float*)d_in[0];
    const float* W_ih  = (const float*)d_in[1];
    const float* b_ih  = (const float*)d_in[2];
    const float* W_hh  = (const float*)d_in[3];
    const float* b_hh  = (const float*)d_in[4];
    const float* W_ho  = (const float*)d_in[5];
    const float* b_ho  = (const float*)d_in[6];
    float* out = (float*)d_out;

    cudaFuncSetAttribute(main_kernel,
                         cudaFuncAttributeMaxDynamicSharedMemorySize, SMEM_BYTES);

    init_kernel<<<512, 256>>>(b_ih);
    forcing_kernel<<<(B_SZ * N_SZ) / 256, 256>>>(batch, W_ih, b_ih);
    main_kernel<<<GRID_MAIN, NTHREADS, SMEM_BYTES>>>(W_hh, b_hh);
    out_kernel<<<B_SZ, 256>>>(W_ho, b_ho, out);
}

// round 10
// speedup vs baseline: 1.1070x; 1.1070x over previous
#include <cuda_runtime.h>
#include <cuda_fp16.h>
#include <math.h>
#include <stdint.h>

#define T_STEPS 256
#define B_SZ    256
#define I_SZ    128
#define N_SZ    1024
#define O_SZ    64
#define M_ROWS  512

#define GRID_MAIN 128
#define BK 64              // k per chunk (halves)
#define NCHUNK (N_SZ / BK) // 16
#define LSTR 33

#define WSTR_H 1032        // W smem row stride (halves)
#define ASTR_H 72          // A smem row stride (halves)
#define ABUF_B 18432       // one A buffer: 128 * 72 * 2
#define NBUF   4

// ---- shared memory byte offsets ----
#define OFF_W     0                        // 32*1032*2 = 66048
#define OFF_A     66048                    // 4 x 18432 = 73728
#define OFF_SLOC  139776                   // 128*33 floats = 16896
#define OFF_XS    156672
#define OFF_KS    173568
#define OFF_FCS   190464
#define OFF_BHS   190592
#define SMEM_BYTES 190720

__device__ __half g_S0[M_ROWS * N_SZ];
__device__ __half g_S1[M_ROWS * N_SZ];
__device__ float  g_X [M_ROWS * N_SZ];
__device__ float  g_F0[B_SZ * N_SZ];
__device__ float  g_fc[N_SZ];
__device__ unsigned g_bar_count[4 * 32];   // per 32-CTA group, 128B apart
__device__ unsigned g_bar_phase[4 * 32];

__constant__ float C_H     = 0.05f;
__constant__ float C_OMEGA = 6.283185307179586f;
__constant__ float C_GAMMA = 0.1f;
__constant__ float C_LAM   = 1.0f;
__constant__ float C_GAIN  = 0.03125f;

// ---------------------------------------------------------------------------
__global__ void init_kernel(const float* __restrict__ b_ih) {
    int idx = blockIdx.x * blockDim.x + threadIdx.x;
    int stride = gridDim.x * blockDim.x;
    for (int i = idx; i < M_ROWS * N_SZ; i += stride) g_S0[i] = __float2half(0.0f);
    if (idx < 4 * 32) { g_bar_count[idx] = 0u; g_bar_phase[idx] = 0u; }
    if (idx < N_SZ) g_fc[idx] = tanhf(b_ih[idx]);
}

__global__ void forcing_kernel(const float* __restrict__ batch,
                               const float* __restrict__ W_ih,
                               const float* __restrict__ b_ih) {
    int idx = blockIdx.x * blockDim.x + threadIdx.x;
    int b = idx >> 10;
    int n = idx & (N_SZ - 1);
    const float4* xp = (const float4*)(batch + b * I_SZ);
    const float4* wp = (const float4*)(W_ih + n * I_SZ);
    float s = 0.0f;
#pragma unroll 8
    for (int i = 0; i < I_SZ / 4; ++i) {
        float4 x = __ldg(xp + i);
        float4 w = __ldg(wp + i);
        s += x.x * w.x + x.y * w.y + x.z * w.z + x.w * w.w;
    }
    g_F0[idx] = tanhf(s + __ldg(b_ih + n));
}

// profiling shim: occupies cycle-position 2 so main_kernel lands on the
// ncu-captured slot (position 3). No work, no memory traffic.
__global__ void shim_kernel() { }

// ---------------------------------------------------------------------------
__device__ __forceinline__ void group_barrier(int grp) {
    __syncthreads();
    if (threadIdx.x == 0) {
        __threadfence();                   // release whole CTA's writes
        volatile unsigned* ph = &g_bar_phase[grp * 32];
        unsigned p = *ph;
        unsigned a = atomicAdd(&g_bar_count[grp * 32], 1u);
        if (a == 31u) {
            atomicExch(&g_bar_count[grp * 32], 0u);
            __threadfence();
            atomicAdd(&g_bar_phase[grp * 32], 1u);
        } else {
            while (*ph == p) { }
        }
        __threadfence();                   // acquire
    }
    __syncthreads();
}

// ---------------------------------------------------------------------------
__device__ __forceinline__ void mma_f16(float* d, uint32_t a0, uint32_t a1,
                                        uint32_t a2, uint32_t a3,
                                        uint32_t b0, uint32_t b1) {
    asm volatile(
        "mma.sync.aligned.m16n8k16.row.col.f32.f16.f16.f32 "
        "{%0,%1,%2,%3},{%4,%5,%6,%7},{%8,%9},{%0,%1,%2,%3};"
        : "+f"(d[0]), "+f"(d[1]), "+f"(d[2]), "+f"(d[3])
        : "r"(a0), "r"(a1), "r"(a2), "r"(a3), "r"(b0), "r"(b1));
}

__device__ __forceinline__ void ldsm4(uint32_t& r0, uint32_t& r1, uint32_t& r2,
                                      uint32_t& r3, uint32_t addr) {
    asm volatile("ldmatrix.sync.aligned.m8n8.x4.shared.b16 {%0,%1,%2,%3}, [%4];"
                 : "=r"(r0), "=r"(r1), "=r"(r2), "=r"(r3) : "r"(addr));
}

__device__ __forceinline__ void cp16(uint32_t s, const void* g) {
    asm volatile("cp.async.cg.shared.global [%0], [%1], 16;"
                 :: "r"(s), "l"(g) : "memory");
}
__device__ __forceinline__ void cp_commit() {
    asm volatile("cp.async.commit_group;" ::: "memory");
}

__device__ __forceinline__ uint32_t smem_u32(const void* p) {
    uint32_t a;
    asm("{ .reg .u64 t; cvta.to.shared.u64 t, %1; cvt.u32.u64 %0, t; }" : "=r"(a) : "l"(p));
    return a;
}

// ---------------------------------------------------------------------------
// main persistent kernel (R6 design + depth-4 cp.async pipeline).
// Grid 128 = 4 independent 32-CTA groups; 256 threads, 8 warps, 16x32 warp tiles.
// ---------------------------------------------------------------------------
__global__ void __launch_bounds__(256, 1)
main_kernel(const float* __restrict__ W_hh, const float* __restrict__ b_hh) {
    extern __shared__ __align__(16) unsigned char smraw[];
    __half* Wsm = (__half*)(smraw + OFF_W);
    float* Sloc = (float*)(smraw + OFF_SLOC);
    float* Xs   = (float*)(smraw + OFF_XS);
    float* Ks   = (float*)(smraw + OFF_KS);
    float* fcs  = (float*)(smraw + OFF_FCS);
    float* bhs  = (float*)(smraw + OFF_BHS);

    const int tid  = threadIdx.x;
    const int lane = tid & 31;
    const int wm   = tid >> 5;
    const int bn   = blockIdx.x & 31;
    const int bm   = blockIdx.x >> 5;
    const int N0   = bn * 32;
    const int batch0 = bm * 64;
    const bool isx = (wm < 4);

    const uint32_t sbase = smem_u32(smraw);
    const uint32_t abase = sbase + OFF_A;

    // ---- one-time: W slice -> smem fp16 ----
    for (int i4 = tid; i4 < 32 * 256; i4 += 256) {
        int r = i4 >> 8, kpos = (i4 & 255) * 4;
        float4 w = __ldg((const float4*)(W_hh + (N0 + r) * N_SZ + kpos));
        __half2* p = (__half2*)(Wsm + r * WSTR_H + kpos);
        p[0] = __floats2half2_rn(w.x, w.y);
        p[1] = __floats2half2_rn(w.z, w.w);
    }
    for (int i = tid; i < 128 * LSTR; i += 256) { Sloc[i] = 0.0f; Xs[i] = 0.0f; Ks[i] = 0.0f; }
    if (tid < 32) { fcs[tid] = g_fc[N0 + tid]; bhs[tid] = __ldg(b_hh + N0 + tid); }
    __syncthreads();

    // ---- cp.async loader mapping: 4 x 16B per thread per chunk ----
    int gofs[4];
    uint32_t sofs[4];
    {
        const int cg = tid & 7;
#pragma unroll
        for (int i = 0; i < 4; ++i) {
            int arow = (tid >> 3) + 32 * i;
            int grow = (arow < 64) ? (batch0 + arow) : (256 + batch0 + arow - 64);
            gofs[i] = grow * N_SZ + cg * 8;
            sofs[i] = (uint32_t)(arow * ASTR_H + cg * 8) * 2;
        }
    }

    // ---- ldmatrix lane addresses ----
    const uint32_t aoff_l =
        (uint32_t)(((wm * 16 + (lane & 7) + ((lane & 8) ? 8 : 0)) * ASTR_H
                    + ((lane & 16) ? 8 : 0)) * 2);
    uint32_t woff[2];
#pragma unroll
    for (int p = 0; p < 2; ++p)
        woff[p] = sbase + OFF_W +
            (uint32_t)(((p * 16 + (lane & 7) + ((lane & 16) ? 8 : 0)) * WSTR_H
                        + ((lane & 8) ? 8 : 0)) * 2);

    __half* const bufs[2] = { g_S0, g_S1 };

    for (int t = 0; t < T_STEPS; ++t) {
        for (int s = 0; s < 4; ++s) {
            const __half* Sin = bufs[s & 1];
            __half*       Sout = bufs[(s + 1) & 1];

            float acc[4][4];
#pragma unroll
            for (int i = 0; i < 4; ++i)
#pragma unroll
                for (int j = 0; j < 4; ++j) acc[i][j] = 0.0f;

            // prologue: chunks 0,1,2
#pragma unroll
            for (int st = 0; st < 3; ++st) {
                const uint32_t ab = abase + st * ABUF_B;
#pragma unroll
                for (int i = 0; i < 4; ++i)
                    cp16(ab + sofs[i], Sin + gofs[i] + st * BK);
                cp_commit();
            }

            for (int c = 0; c < NCHUNK; ++c) {
                // wait for chunk c: allowed outstanding = min(2, NCHUNK-1-c)
                if (c + 2 < NCHUNK)
                    asm volatile("cp.async.wait_group 2;" ::: "memory");
                else if (c + 1 < NCHUNK)
                    asm volatile("cp.async.wait_group 1;" ::: "memory");
                else
                    asm volatile("cp.async.wait_group 0;" ::: "memory");
                __syncthreads();

                if (c + 3 < NCHUNK) {
                    const int st = c + 3;
                    const uint32_t ab = abase + (st & (NBUF - 1)) * ABUF_B;
#pragma unroll
                    for (int i = 0; i < 4; ++i)
                        cp16(ab + sofs[i], Sin + gofs[i] + st * BK);
                    cp_commit();
                }

                const uint32_t ab = abase + (c & (NBUF - 1)) * ABUF_B;
                const uint32_t wk = (uint32_t)(c * BK * 2);
#pragma unroll
                for (int kk = 0; kk < BK; kk += 16) {
                    uint32_t a0, a1, a2, a3;
                    ldsm4(a0, a1, a2, a3, ab + aoff_l + kk * 2);
                    uint32_t b00, b01, b10, b11;
                    ldsm4(b00, b01, b10, b11, woff[0] + wk + kk * 2);
                    uint32_t b20, b21, b30, b31;
                    ldsm4(b20, b21, b30, b31, woff[1] + wk + kk * 2);
                    mma_f16(acc[0], a0, a1, a2, a3, b00, b01);
                    mma_f16(acc[1], a0, a1, a2, a3, b10, b11);
                    mma_f16(acc[2], a0, a1, a2, a3, b20, b21);
                    mma_f16(acc[3], a0, a1, a2, a3, b30, b31);
                }
            }

            // ---------------- fused RK4-stage epilogue (SMEM-local state) -------
            const float cmul = (s == 2) ? C_H : 0.5f * C_H;
            const int r0 = wm * 16 + (lane >> 2);
            float kv[4][4];
#pragma unroll
            for (int nt = 0; nt < 4; ++nt) {
#pragma unroll
                for (int e = 0; e < 4; ++e) {
                    const int rl = r0 + 8 * (e >> 1);
                    const int cl = nt * 8 + 2 * (lane & 3) + (e & 1);
                    const int rx = isx ? rl : rl - 64;
                    const float sx = Sloc[rx * LSTR + cl];
                    const float sy = Sloc[(rx + 64) * LSTR + cl];
                    const float amp = C_LAM - (sx * sx + sy * sy);
                    const float rr = acc[nt][e];
                    float k;
                    if (isx) {
                        float F = (t == 0) ? g_F0[(batch0 + rx) * N_SZ + N0 + cl] : fcs[cl];
                        k = amp * sx - C_OMEGA * sy + C_GAIN * (rr + bhs[cl]) + F - C_GAMMA * sx;
                    } else {
                        k = amp * sy + C_OMEGA * sx + C_GAIN * (rr + bhs[cl]) - C_GAMMA * sy;
                    }
                    kv[nt][e] = k;
                }
            }
            __syncthreads();  // all Sloc reads done before overwrites
#pragma unroll
            for (int nt = 0; nt < 4; ++nt) {
#pragma unroll
                for (int eh = 0; eh < 2; ++eh) {
                    const int rl  = r0 + 8 * eh;
                    const int cl0 = nt * 8 + 2 * (lane & 3);
                    float sv[2];
#pragma unroll
                    for (int j = 0; j < 2; ++j) {
                        const int il = rl * LSTR + cl0 + j;
                        const float k = kv[nt][eh * 2 + j];
                        const float xv = Xs[il];
                        float v;
                        if (s == 0)      { Ks[il] = k;                        v = xv + cmul * k; }
                        else if (s == 3) { float xn = xv + (C_H / 6.0f) * (Ks[il] + k);
                                           Xs[il] = xn;                       v = xn; }
                        else             { Ks[il] += 2.0f * k;                v = xv + cmul * k; }
                        Sloc[il] = v;
                        sv[j] = v;
                    }
                    const int grow = batch0 + rl + (isx ? 0 : 192);
                    const int gi = grow * N_SZ + N0 + cl0;
                    *(__half2*)(Sout + gi) = __floats2half2_rn(sv[0], sv[1]);
                    if (t == T_STEPS - 1 && s == 3)
                        *(float2*)(g_X + gi) = make_float2(sv[0], sv[1]);
                }
            }
            group_barrier(bm);
        }
    }
}

// ---------------------------------------------------------------------------
__global__ void out_kernel(const float* __restrict__ W_ho,
                           const float* __restrict__ b_ho,
                           float* __restrict__ out) {
    int b   = blockIdx.x;
    int tid = threadIdx.x;
    int o   = tid >> 2;
    int q   = tid & 3;
    const float4* xp = (const float4*)(g_X + b * N_SZ + q * 256);
    const float4* wp = (const float4*)(W_ho + o * N_SZ + q * 256);
    float s = 0.0f;
#pragma unroll 8
    for (int i = 0; i < 64; ++i) {
        float4 x = xp[i];
        float4 w = __ldg(wp + i);
        s += x.x * w.x + x.y * w.y + x.z * w.z + x.w * w.w;
    }
    s += __shfl_xor_sync(0xffffffffu, s, 1);
    s += __shfl_xor_sync(0xffffffffu, s, 2);
    if (q == 0) out[b * O_SZ + o] = s + __ldg(b_ho + o);
}

// ---------------------------------------------------------------------------
extern "C" void kernel_launch(void* const* d_in, const int* in_sizes, int n_in,
                              void* d_out, int out_size) {
    const float* batch = (const float*)d_in[0];
    const float* W_ih  = (const float*)d_in[1];
    const float* b_ih  = (const float*)d_in[2];
    const float* W_hh  = (const float*)d_in[3];
    const float* b_hh  = (const float*)d_in[4];
    const float* W_ho  = (const float*)d_in[5];
    const float* b_ho  = (const float*)d_in[6];
    float* out = (float*)d_out;

    cudaFuncSetAttribute(main_kernel,
                         cudaFuncAttributeMaxDynamicSharedMemorySize, SMEM_BYTES);

    init_kernel<<<512, 256>>>(b_ih);
    forcing_kernel<<<(B_SZ * N_SZ) / 256, 256>>>(batch, W_ih, b_ih);
    shim_kernel<<<1, 32>>>();   // shifts main_kernel onto the ncu-captured slot
    main_kernel<<<GRID_MAIN, 256, SMEM_BYTES>>>(W_hh, b_hh);
    out_kernel<<<B_SZ, 256>>>(W_ho, b_ho, out);
}

// round 11
// speedup vs baseline: 1.3315x; 1.2028x over previous
#include <cuda_runtime.h>
#include <cuda_fp16.h>
#include <math.h>
#include <stdint.h>

#define T_STEPS 256
#define B_SZ    256
#define I_SZ    128
#define N_SZ    1024
#define O_SZ    64
#define M_ROWS  512

#define GRID_MAIN 128
#define NCHUNK  16
#define LSTR 33

#define WSTR_H 1032        // W smem row stride (halves)

// ---- shared memory byte offsets ----
#define OFF_W     0                        // 32*1032*2 = 66048
#define OFF_SLOC  66048                    // 128*33 floats = 16896
#define OFF_XS    82944
#define OFF_KS    99840
#define OFF_FCS   116736
#define OFF_BHS   116864
#define SMEM_BYTES 116992

// state ping-pong buffers in FRAGMENT-MAJOR layout:
// uint4 index = s16*2048 + c*128 + kk4*32 + lane
//   s16 = mgroup*8 + strip (0..31), c = chunk (0..15), kk4 = k16-window (0..3)
// each uint4 = the 4 A-operand words of one lane for one m16n8k16 mma.
__device__ __align__(16) uint4 g_S0[32 * 2048];
__device__ __align__(16) uint4 g_S1[32 * 2048];
__device__ float  g_X [M_ROWS * N_SZ];
__device__ float  g_F0[B_SZ * N_SZ];
__device__ float  g_fc[N_SZ];
__device__ unsigned g_bar_count[4 * 32];
__device__ unsigned g_bar_phase[4 * 32];

__constant__ float C_H     = 0.05f;
__constant__ float C_OMEGA = 6.283185307179586f;
__constant__ float C_GAMMA = 0.1f;
__constant__ float C_LAM   = 1.0f;
__constant__ float C_GAIN  = 0.03125f;

// ---------------------------------------------------------------------------
__global__ void init_kernel(const float* __restrict__ b_ih) {
    int idx = blockIdx.x * blockDim.x + threadIdx.x;
    int stride = gridDim.x * blockDim.x;
    uint4 z = make_uint4(0u, 0u, 0u, 0u);
    for (int i = idx; i < 32 * 2048; i += stride) g_S0[i] = z;
    if (idx < 4 * 32) { g_bar_count[idx] = 0u; g_bar_phase[idx] = 0u; }
    if (idx < N_SZ) g_fc[idx] = tanhf(b_ih[idx]);
}

__global__ void forcing_kernel(const float* __restrict__ batch,
                               const float* __restrict__ W_ih,
                               const float* __restrict__ b_ih) {
    int idx = blockIdx.x * blockDim.x + threadIdx.x;
    int b = idx >> 10;
    int n = idx & (N_SZ - 1);
    const float4* xp = (const float4*)(batch + b * I_SZ);
    const float4* wp = (const float4*)(W_ih + n * I_SZ);
    float s = 0.0f;
#pragma unroll 8
    for (int i = 0; i < I_SZ / 4; ++i) {
        float4 x = __ldg(xp + i);
        float4 w = __ldg(wp + i);
        s += x.x * w.x + x.y * w.y + x.z * w.z + x.w * w.w;
    }
    g_F0[idx] = tanhf(s + __ldg(b_ih + n));
}

// profiling shim: keeps main_kernel on the ncu-captured launch slot.
__global__ void shim_kernel() { }

// ---------------------------------------------------------------------------
__device__ __forceinline__ void group_barrier(int grp) {
    __syncthreads();
    if (threadIdx.x == 0) {
        __threadfence();
        volatile unsigned* ph = &g_bar_phase[grp * 32];
        unsigned p = *ph;
        unsigned a = atomicAdd(&g_bar_count[grp * 32], 1u);
        if (a == 31u) {
            atomicExch(&g_bar_count[grp * 32], 0u);
            __threadfence();
            atomicAdd(&g_bar_phase[grp * 32], 1u);
        } else {
            while (*ph == p) { }
        }
        __threadfence();
    }
    __syncthreads();
}

// ---------------------------------------------------------------------------
__device__ __forceinline__ void mma_f16(float* d, uint32_t a0, uint32_t a1,
                                        uint32_t a2, uint32_t a3,
                                        uint32_t b0, uint32_t b1) {
    asm volatile(
        "mma.sync.aligned.m16n8k16.row.col.f32.f16.f16.f32 "
        "{%0,%1,%2,%3},{%4,%5,%6,%7},{%8,%9},{%0,%1,%2,%3};"
        : "+f"(d[0]), "+f"(d[1]), "+f"(d[2]), "+f"(d[3])
        : "r"(a0), "r"(a1), "r"(a2), "r"(a3), "r"(b0), "r"(b1));
}

__device__ __forceinline__ void ldsm4(uint32_t& r0, uint32_t& r1, uint32_t& r2,
                                      uint32_t& r3, uint32_t addr) {
    asm volatile("ldmatrix.sync.aligned.m8n8.x4.shared.b16 {%0,%1,%2,%3}, [%4];"
                 : "=r"(r0), "=r"(r1), "=r"(r2), "=r"(r3) : "r"(addr));
}

__device__ __forceinline__ uint32_t smem_u32(const void* p) {
    uint32_t a;
    asm("{ .reg .u64 t; cvta.to.shared.u64 t, %1; cvt.u32.u64 %0, t; }" : "=r"(a) : "l"(p));
    return a;
}

// ---------------------------------------------------------------------------
// main persistent kernel — fragment-major A, no mainloop syncthreads.
// Grid 128 = 4 independent 32-CTA groups; 8 warps x (16m x 32n) tiles.
// ---------------------------------------------------------------------------
__global__ void __launch_bounds__(256, 1)
main_kernel(const float* __restrict__ W_hh, const float* __restrict__ b_hh) {
    extern __shared__ __align__(16) unsigned char smraw[];
    __half* Wsm = (__half*)(smraw + OFF_W);
    float* Sloc = (float*)(smraw + OFF_SLOC);
    float* Xs   = (float*)(smraw + OFF_XS);
    float* Ks   = (float*)(smraw + OFF_KS);
    float* fcs  = (float*)(smraw + OFF_FCS);
    float* bhs  = (float*)(smraw + OFF_BHS);

    const int tid  = threadIdx.x;
    const int lane = tid & 31;
    const int wm   = tid >> 5;
    const int bn   = blockIdx.x & 31;
    const int bm   = blockIdx.x >> 5;
    const int N0   = bn * 32;
    const int batch0 = bm * 64;
    const bool isx = (wm < 4);

    const uint32_t sbase = smem_u32(smraw);

    // ---- one-time: W slice -> smem fp16 ----
    for (int i4 = tid; i4 < 32 * 256; i4 += 256) {
        int r = i4 >> 8, kpos = (i4 & 255) * 4;
        float4 w = __ldg((const float4*)(W_hh + (N0 + r) * N_SZ + kpos));
        __half2* p = (__half2*)(Wsm + r * WSTR_H + kpos);
        p[0] = __floats2half2_rn(w.x, w.y);
        p[1] = __floats2half2_rn(w.z, w.w);
    }
    for (int i = tid; i < 128 * LSTR; i += 256) { Sloc[i] = 0.0f; Xs[i] = 0.0f; Ks[i] = 0.0f; }
    if (tid < 32) { fcs[tid] = g_fc[N0 + tid]; bhs[tid] = __ldg(b_hh + N0 + tid); }
    __syncthreads();

    // ---- ldmatrix lane addresses for W ----
    uint32_t woff[2];
#pragma unroll
    for (int p = 0; p < 2; ++p)
        woff[p] = sbase + OFF_W +
            (uint32_t)(((p * 16 + (lane & 7) + ((lane & 16) ? 8 : 0)) * WSTR_H
                        + ((lane & 8) ? 8 : 0)) * 2);

    // fragment-major base index for this warp's strip (uint4 units)
    const int fstrip = (bm * 8 + wm) * 2048 + lane;
    // epilogue store chunk/kk4 base
    const int ec   = bn >> 1;            // chunk written by this CTA
    const int ekk0 = (bn & 1) * 2;       // kk4 base (p adds 0/1)

    uint4* const bufs[2] = { g_S0, g_S1 };

    for (int t = 0; t < T_STEPS; ++t) {
        for (int s = 0; s < 4; ++s) {
            const uint4* Ain = bufs[s & 1];
            uint4*       Aout = bufs[(s + 1) & 1];

            float acc[4][4];
#pragma unroll
            for (int i = 0; i < 4; ++i)
#pragma unroll
                for (int j = 0; j < 4; ++j) acc[i][j] = 0.0f;

            uint4 cur[4], nx1[4], nx2[4];
#pragma unroll
            for (int k4 = 0; k4 < 4; ++k4)
                cur[k4] = __ldcg(Ain + fstrip + k4 * 32);
#pragma unroll
            for (int k4 = 0; k4 < 4; ++k4)
                nx1[k4] = __ldcg(Ain + fstrip + 128 + k4 * 32);

            for (int c = 0; c < NCHUNK; ++c) {
                if (c + 2 < NCHUNK) {
                    const int fo = fstrip + (c + 2) * 128;
#pragma unroll
                    for (int k4 = 0; k4 < 4; ++k4)
                        nx2[k4] = __ldcg(Ain + fo + k4 * 32);
                }

                const uint32_t wk = (uint32_t)(c * 128);   // bytes into W row
#pragma unroll
                for (int k4 = 0; k4 < 4; ++k4) {
                    uint32_t b00, b01, b10, b11;
                    ldsm4(b00, b01, b10, b11, woff[0] + wk + k4 * 32);
                    uint32_t b20, b21, b30, b31;
                    ldsm4(b20, b21, b30, b31, woff[1] + wk + k4 * 32);
                    mma_f16(acc[0], cur[k4].x, cur[k4].y, cur[k4].z, cur[k4].w, b00, b01);
                    mma_f16(acc[1], cur[k4].x, cur[k4].y, cur[k4].z, cur[k4].w, b10, b11);
                    mma_f16(acc[2], cur[k4].x, cur[k4].y, cur[k4].z, cur[k4].w, b20, b21);
                    mma_f16(acc[3], cur[k4].x, cur[k4].y, cur[k4].z, cur[k4].w, b30, b31);
                }
#pragma unroll
                for (int k4 = 0; k4 < 4; ++k4) { cur[k4] = nx1[k4]; nx1[k4] = nx2[k4]; }
            }

            // ---------------- fused RK4-stage epilogue (SMEM-local state) -------
            const float cmul = (s == 2) ? C_H : 0.5f * C_H;
            const int r0 = wm * 16 + (lane >> 2);
            float kv[4][4];
#pragma unroll
            for (int nt = 0; nt < 4; ++nt) {
#pragma unroll
                for (int e = 0; e < 4; ++e) {
                    const int rl = r0 + 8 * (e >> 1);
                    const int cl = nt * 8 + 2 * (lane & 3) + (e & 1);
                    const int rx = isx ? rl : rl - 64;
                    const float sx = Sloc[rx * LSTR + cl];
                    const float sy = Sloc[(rx + 64) * LSTR + cl];
                    const float amp = C_LAM - (sx * sx + sy * sy);
                    const float rr = acc[nt][e];
                    float k;
                    if (isx) {
                        float F = (t == 0) ? g_F0[(batch0 + rx) * N_SZ + N0 + cl] : fcs[cl];
                        k = amp * sx - C_OMEGA * sy + C_GAIN * (rr + bhs[cl]) + F - C_GAMMA * sx;
                    } else {
                        k = amp * sy + C_OMEGA * sx + C_GAIN * (rr + bhs[cl]) - C_GAMMA * sy;
                    }
                    kv[nt][e] = k;
                }
            }
            __syncthreads();  // all Sloc reads done before overwrites

            uint32_t vreg[2][4];
#pragma unroll
            for (int nt = 0; nt < 4; ++nt) {
#pragma unroll
                for (int eh = 0; eh < 2; ++eh) {
                    const int rl  = r0 + 8 * eh;
                    const int cl0 = nt * 8 + 2 * (lane & 3);
                    float sv[2];
#pragma unroll
                    for (int j = 0; j < 2; ++j) {
                        const int il = rl * LSTR + cl0 + j;
                        const float k = kv[nt][eh * 2 + j];
                        const float xv = Xs[il];
                        float v;
                        if (s == 0)      { Ks[il] = k;                        v = xv + cmul * k; }
                        else if (s == 3) { float xn = xv + (C_H / 6.0f) * (Ks[il] + k);
                                           Xs[il] = xn;                       v = xn; }
                        else             { Ks[il] += 2.0f * k;                v = xv + cmul * k; }
                        Sloc[il] = v;
                        sv[j] = v;
                    }
                    __half2 h2 = __floats2half2_rn(sv[0], sv[1]);
                    vreg[nt >> 1][eh + 2 * (nt & 1)] = *reinterpret_cast<uint32_t*>(&h2);
                    if (t == T_STEPS - 1 && s == 3) {
                        const int grow = batch0 + rl + (isx ? 0 : 192);
                        *(float2*)(g_X + grow * N_SZ + N0 + cl0) = make_float2(sv[0], sv[1]);
                    }
                }
            }
            // two coalesced ST.128 into the consumer fragment layout
#pragma unroll
            for (int p = 0; p < 2; ++p) {
                const int idx = (bm * 8 + wm) * 2048 + ec * 128 + (ekk0 + p) * 32 + lane;
                Aout[idx] = make_uint4(vreg[p][0], vreg[p][1], vreg[p][2], vreg[p][3]);
            }
            group_barrier(bm);
        }
    }
}

// ---------------------------------------------------------------------------
__global__ void out_kernel(const float* __restrict__ W_ho,
                           const float* __restrict__ b_ho,
                           float* __restrict__ out) {
    int b   = blockIdx.x;
    int tid = threadIdx.x;
    int o   = tid >> 2;
    int q   = tid & 3;
    const float4* xp = (const float4*)(g_X + b * N_SZ + q * 256);
    const float4* wp = (const float4*)(W_ho + o * N_SZ + q * 256);
    float s = 0.0f;
#pragma unroll 8
    for (int i = 0; i < 64; ++i) {
        float4 x = xp[i];
        float4 w = __ldg(wp + i);
        s += x.x * w.x + x.y * w.y + x.z * w.z + x.w * w.w;
    }
    s += __shfl_xor_sync(0xffffffffu, s, 1);
    s += __shfl_xor_sync(0xffffffffu, s, 2);
    if (q == 0) out[b * O_SZ + o] = s + __ldg(b_ho + o);
}

// ---------------------------------------------------------------------------
extern "C" void kernel_launch(void* const* d_in, const int* in_sizes, int n_in,
                              void* d_out, int out_size) {
    const float* batch = (const float*)d_in[0];
    const float* W_ih  = (const float*)d_in[1];
    const float* b_ih  = (const float*)d_in[2];
    const float* W_hh  = (const float*)d_in[3];
    const float* b_hh  = (const float*)d_in[4];
    const float* W_ho  = (const float*)d_in[5];
    const float* b_ho  = (const float*)d_in[6];
    float* out = (float*)d_out;

    cudaFuncSetAttribute(main_kernel,
                         cudaFuncAttributeMaxDynamicSharedMemorySize, SMEM_BYTES);

    init_kernel<<<512, 256>>>(b_ih);
    forcing_kernel<<<(B_SZ * N_SZ) / 256, 256>>>(batch, W_ih, b_ih);
    shim_kernel<<<1, 32>>>();
    main_kernel<<<GRID_MAIN, 256, SMEM_BYTES>>>(W_hh, b_hh);
    out_kernel<<<B_SZ, 256>>>(W_ho, b_ho, out);
}